// round 10
// baseline (speedup 1.0000x reference)
#include <cuda_runtime.h>
#include <math.h>
#include <stdint.h>

// ---------------------------------------------------------------------------
// LinearAttention:
//   k_qkv_mma : TF32 mma.sync GEMM (compute_100-legal tensor core path)
//               + elu + per-tile kv reductions
//   k_scale   : deterministic finalize
//   k_out     : measured-good f32x2-FFMA GEMM + fused LayerNorm (round-3 ver.)
// ---------------------------------------------------------------------------

using u64 = unsigned long long;

#define NB   16
#define NC   256
#define NPIX 4096
#define PTILES_PER_B 32
#define NTILES (NB * PTILES_PER_B)

__device__ float g_qk[(size_t)NB * NC * NPIX];   // elu1(q), [b][c][pix]
__device__ float g_part_kv[NTILES][NC];
__device__ float g_part_kk[NTILES][NC];
__device__ float g_scale[NB * NC];

// ------------------------------ helpers ------------------------------------
__device__ __forceinline__ u64 pack2(float x, float y) {
    u64 r; asm("mov.b64 %0, {%1, %2};" : "=l"(r) : "f"(x), "f"(y)); return r;
}
__device__ __forceinline__ void unpack2(u64 v, float &x, float &y) {
    asm("mov.b64 {%0, %1}, %2;" : "=f"(x), "=f"(y) : "l"(v));
}
__device__ __forceinline__ void ffma2(u64 &d, u64 a, u64 b) {
    asm("fma.rn.f32x2 %0, %1, %2, %0;" : "+l"(d) : "l"(a), "l"(b));
}
__device__ __forceinline__ float elu1(float v) { return v > 0.0f ? v + 1.0f : expf(v); }

__device__ __forceinline__ uint32_t f2tf32(float x) {
    uint32_t r; asm("cvt.rna.tf32.f32 %0, %1;" : "=r"(r) : "f"(x)); return r;
}

// m16n8k8 TF32 mma, D += A*B (fp32 accum)
__device__ __forceinline__ void mma_tf32(float* d, const uint32_t* a, const uint32_t* b) {
    asm volatile(
        "mma.sync.aligned.m16n8k8.row.col.f32.tf32.tf32.f32 "
        "{%0,%1,%2,%3}, {%4,%5,%6,%7}, {%8,%9}, {%0,%1,%2,%3};"
        : "+f"(d[0]), "+f"(d[1]), "+f"(d[2]), "+f"(d[3])
        : "r"(a[0]), "r"(a[1]), "r"(a[2]), "r"(a[3]), "r"(b[0]), "r"(b[1]));
}

// ===========================================================================
// Kernel 1: TF32 mma QKV GEMM + elu + partial reductions
//   grid (8, 512) = (channel group g: 32 oc per q/k/v section, pixel tile t)
//   block 256 = 8 warps: warp = (ochalf: which 16-row half) x (pxq: 32-px quarter)
//   Per warp: 3 m16-tiles (one per section) x 4 n8-tiles x K=256.
// ===========================================================================
__global__ __launch_bounds__(256, 2)
void k_qkv_mma(const float* __restrict__ x, const float* __restrict__ w_qkv)
{
    // fragment-permuted staging (per kc=32 chunk)
    __shared__ alignas(16) uint32_t Wf[24 * 128];  // 24 m16k8 tiles, 12 KB
    __shared__ alignas(16) uint32_t Xf[64 * 64];   // 64 k8n8 tiles, 16 KB
    __shared__ float red_kk[32][4], red_kv[32][4];

    const int g    = blockIdx.x;            // 0..7
    const int t    = blockIdx.y;            // 0..511
    const int b    = t >> 5;
    const int p0   = (t & 31) << 7;
    const int tid  = threadIdx.x;
    const int wid  = tid >> 5, lane = tid & 31;
    const int ochalf = wid >> 2;            // 0..1
    const int pxq    = wid & 3;             // 0..3 -> pixels pxq*32..+31
    const int grp = lane >> 2, tig = lane & 3;

    float acc[3][4][4];                     // [section][n-tile][c-reg]
#pragma unroll
    for (int s = 0; s < 3; s++)
#pragma unroll
        for (int n = 0; n < 4; n++)
#pragma unroll
            for (int c = 0; c < 4; c++) acc[s][n][c] = 0.0f;

    const float* xb = x + (size_t)b * NC * NPIX + p0;

    for (int kc = 0; kc < 8; kc++) {
        // ---- stage W chunk [96 rows][32 k] into fragment order ----
#pragma unroll
        for (int r = 0; r < 3; r++) {
            int idx = tid + 256 * r;        // 0..767
            int row = idx >> 3, q4 = idx & 7;
            int sec = row >> 5, ocl = row & 31;
            const float* wp = w_qkv + (size_t)(sec * 256 + g * 32 + ocl) * 256 + kc * 32 + q4 * 4;
            float4 v = *(const float4*)wp;
            int ks    = q4 >> 1;            // k8 index
            int wrow  = row & 15;
            int rtile = (row >> 4) & 1;
            int tile  = (sec * 2 + rtile) * 4 + ks;
            int reg   = (wrow >> 3) + 2 * (q4 & 1);
            uint32_t base = (uint32_t)(tile * 128 + (wrow & 7) * 16 + reg);
            Wf[base]      = f2tf32(v.x);    // lane stride 4 words per col
            Wf[base + 4]  = f2tf32(v.y);
            Wf[base + 8]  = f2tf32(v.z);
            Wf[base + 12] = f2tf32(v.w);
        }
        // ---- stage X chunk [32 k][128 px] into fragment order ----
#pragma unroll
        for (int r = 0; r < 4; r++) {
            int idx = tid + 256 * r;        // 0..1023
            int krow = idx >> 5, p4 = idx & 31;
            float4 v = *(const float4*)(xb + (size_t)(kc * 32 + krow) * NPIX + p4 * 4);
            int ks = krow >> 3, kin = krow & 7;
            int px = p4 * 4;
            int pt = px >> 3, n0 = px & 7;  // n0 in {0,4}
            int tile = ks * 16 + pt;
            int reg  = kin >> 2;
            uint32_t base = (uint32_t)(tile * 64 + (n0 * 4 + (kin & 3)) * 2 + reg);
            Xf[base]      = f2tf32(v.x);    // lane stride 8 words per n
            Xf[base + 8]  = f2tf32(v.y);
            Xf[base + 16] = f2tf32(v.z);
            Xf[base + 24] = f2tf32(v.w);
        }
        __syncthreads();

#pragma unroll
        for (int ks = 0; ks < 4; ks++) {
            uint32_t a[3][4], bf[4][2];
#pragma unroll
            for (int s = 0; s < 3; s++)
                *(uint4*)a[s] = *(const uint4*)&Wf[((s * 2 + ochalf) * 4 + ks) * 128 + lane * 4];
#pragma unroll
            for (int n = 0; n < 4; n++)
                *(uint2*)bf[n] = *(const uint2*)&Xf[(ks * 16 + pxq * 4 + n) * 64 + lane * 2];
#pragma unroll
            for (int s = 0; s < 3; s++)
#pragma unroll
                for (int n = 0; n < 4; n++)
                    mma_tf32(acc[s][n], a[s], bf[n]);
        }
        __syncthreads();
    }

    // ---------------- q epilogue: elu -> g_qk ----------------
    {
        int oc = g * 32 + ochalf * 16 + grp;
        float* dst0 = g_qk + ((size_t)(b * NC + oc)) * NPIX + p0 + pxq * 32;
        float* dst1 = dst0 + (size_t)8 * NPIX;   // row grp+8
#pragma unroll
        for (int n = 0; n < 4; n++) {
            int px = n * 8 + tig * 2;
            float2 lo, hi;
            lo.x = elu1(acc[0][n][0]); lo.y = elu1(acc[0][n][1]);
            hi.x = elu1(acc[0][n][2]); hi.y = elu1(acc[0][n][3]);
            *(float2*)(dst0 + px) = lo;
            *(float2*)(dst1 + px) = hi;
        }
    }

    // ---------------- k/v epilogue: partial sums ----------------
    float skk0 = 0.0f, skk1 = 0.0f, skv0 = 0.0f, skv1 = 0.0f;
#pragma unroll
    for (int n = 0; n < 4; n++) {
        float ek;
        ek = elu1(acc[1][n][0]); skk0 += ek; skv0 += ek * acc[2][n][0];
        ek = elu1(acc[1][n][1]); skk0 += ek; skv0 += ek * acc[2][n][1];
        ek = elu1(acc[1][n][2]); skk1 += ek; skv1 += ek * acc[2][n][2];
        ek = elu1(acc[1][n][3]); skk1 += ek; skv1 += ek * acc[2][n][3];
    }
#pragma unroll
    for (int off = 1; off < 4; off <<= 1) {
        skk0 += __shfl_xor_sync(0xFFFFFFFFu, skk0, off);
        skk1 += __shfl_xor_sync(0xFFFFFFFFu, skk1, off);
        skv0 += __shfl_xor_sync(0xFFFFFFFFu, skv0, off);
        skv1 += __shfl_xor_sync(0xFFFFFFFFu, skv1, off);
    }
    if (tig == 0) {
        int r = ochalf * 16 + grp;
        red_kk[r][pxq]     = skk0;  red_kv[r][pxq]     = skv0;
        red_kk[r + 8][pxq] = skk1;  red_kv[r + 8][pxq] = skv1;
    }
    __syncthreads();
    if (tid < 32) {
        float kk = red_kk[tid][0] + red_kk[tid][1] + red_kk[tid][2] + red_kk[tid][3];
        float kv = red_kv[tid][0] + red_kv[tid][1] + red_kv[tid][2] + red_kv[tid][3];
        g_part_kk[t][g * 32 + tid] = kk;
        g_part_kv[t][g * 32 + tid] = kv;
    }
}

// ===========================================================================
// Kernel 2: finalize scale[b][c]  (deterministic serial sum)
// ===========================================================================
__global__ void k_scale_fin()
{
    int idx = blockIdx.x * 256 + threadIdx.x;
    int b = idx >> 8, c = idx & 255;
    float skv = 0.0f, skk = 0.0f;
#pragma unroll
    for (int i = 0; i < PTILES_PER_B; i++) {
        skv += g_part_kv[b * PTILES_PER_B + i][c];
        skk += g_part_kk[b * PTILES_PER_B + i][c];
    }
    g_scale[idx] = skv / fmaxf(skk, 1e-6f);
}

// ===========================================================================
// Kernel 3: out GEMM + fused LayerNorm (round-3 measured version)
// ===========================================================================
__global__ __launch_bounds__(256, 2)
void k_out(const float* __restrict__ w_out, const float* __restrict__ gamma,
           const float* __restrict__ beta, float* __restrict__ out)
{
    __shared__ alignas(16) float As[32][64];
    __shared__ alignas(16) float Bs[32][257];
    __shared__ float sscale[256], sgamma[256], sbeta[256];
    __shared__ float smu[64], srstd[64];

    const int blk  = blockIdx.x;
    const int b    = blk >> 6;
    const int p0   = (blk & 63) << 6;
    const int tid  = threadIdx.x;
    const int pixT = tid & 7;
    const int ocT  = tid >> 3;
    const int lane = tid & 31;
    const int warp = tid >> 5;

    sscale[tid] = g_scale[b * NC + tid];
    sgamma[tid] = gamma[tid];
    sbeta[tid]  = beta[tid];
    __syncthreads();

    u64 acc[8][4];
#pragma unroll
    for (int j = 0; j < 8; j++)
#pragma unroll
        for (int i = 0; i < 4; i++) acc[j][i] = 0ull;

    const float* qb = g_qk + (size_t)b * NC * NPIX + p0;

    for (int kc = 0; kc < 256; kc += 32) {
#pragma unroll
        for (int r = 0; r < 2; r++) {
            int f = tid + 256 * r;
            int k = f >> 4, q = f & 15;
            float4 v = *(const float4*)(qb + (size_t)(kc + k) * NPIX + q * 4);
            float s = sscale[kc + k];
            v.x *= s; v.y *= s; v.z *= s; v.w *= s;
            *(float4*)&As[k][q * 4] = v;
        }
#pragma unroll
        for (int r = 0; r < 8; r++) {
            int f = tid + 256 * r;
            int o = f >> 3, q = f & 7;
            float4 v = *(const float4*)(w_out + (size_t)o * 256 + kc + q * 4);
            Bs[q * 4 + 0][o] = v.x;
            Bs[q * 4 + 1][o] = v.y;
            Bs[q * 4 + 2][o] = v.z;
            Bs[q * 4 + 3][o] = v.w;
        }
        __syncthreads();

#pragma unroll 8
        for (int kk = 0; kk < 32; kk++) {
            u64 av[4];
#pragma unroll
            for (int i = 0; i < 4; i++)
                av[i] = *(const u64*)&As[kk][16 * i + 2 * pixT];
#pragma unroll
            for (int j = 0; j < 8; j++) {
                float bs = Bs[kk][ocT * 8 + j];
                u64 bv = pack2(bs, bs);
#pragma unroll
                for (int i = 0; i < 4; i++) ffma2(acc[j][i], av[i], bv);
            }
        }
        __syncthreads();
    }

    float ps[4][2], pss[4][2];
#pragma unroll
    for (int i = 0; i < 4; i++) { ps[i][0] = ps[i][1] = 0.0f; pss[i][0] = pss[i][1] = 0.0f; }
#pragma unroll
    for (int j = 0; j < 8; j++)
#pragma unroll
        for (int i = 0; i < 4; i++) {
            float v0, v1; unpack2(acc[j][i], v0, v1);
            ps[i][0] += v0;  pss[i][0] += v0 * v0;
            ps[i][1] += v1;  pss[i][1] += v1 * v1;
        }
#pragma unroll
    for (int off = 8; off < 32; off <<= 1)
#pragma unroll
        for (int i = 0; i < 4; i++) {
            ps[i][0]  += __shfl_xor_sync(0xFFFFFFFFu, ps[i][0],  off);
            ps[i][1]  += __shfl_xor_sync(0xFFFFFFFFu, ps[i][1],  off);
            pss[i][0] += __shfl_xor_sync(0xFFFFFFFFu, pss[i][0], off);
            pss[i][1] += __shfl_xor_sync(0xFFFFFFFFu, pss[i][1], off);
        }
    float (*redA)[64] = (float(*)[64])&As[0][0];
    float (*redB)[64] = (float(*)[64])&As[16][0];
    __syncthreads();
    if (lane < 8) {
#pragma unroll
        for (int i = 0; i < 4; i++) {
            int p = 16 * i + 2 * lane;
            redA[warp][p]     = ps[i][0];
            redA[warp][p + 1] = ps[i][1];
            redB[warp][p]     = pss[i][0];
            redB[warp][p + 1] = pss[i][1];
        }
    }
    __syncthreads();
    if (tid < 64) {
        float s = 0.0f, ss = 0.0f;
#pragma unroll
        for (int w = 0; w < 8; w++) { s += redA[w][tid]; ss += redB[w][tid]; }
        float mu  = s * (1.0f / 256.0f);
        float var = ss * (1.0f / 256.0f) - mu * mu;
        smu[tid]   = mu;
        srstd[tid] = rsqrtf(var + 1e-5f);
    }
    __syncthreads();

    float* ob = out + (size_t)b * NC * NPIX + p0;
#pragma unroll
    for (int j = 0; j < 8; j++) {
        int oc = ocT * 8 + j;
        float gm = sgamma[oc], bt = sbeta[oc];
        float* dst = ob + (size_t)oc * NPIX;
#pragma unroll
        for (int i = 0; i < 4; i++) {
            int p = 16 * i + 2 * pixT;
            float v0, v1; unpack2(acc[j][i], v0, v1);
            float2 o2;
            o2.x = (v0 - smu[p])     * srstd[p]     * gm + bt;
            o2.y = (v1 - smu[p + 1]) * srstd[p + 1] * gm + bt;
            *(float2*)(dst + p) = o2;
        }
    }
}

// ===========================================================================
extern "C" void kernel_launch(void* const* d_in, const int* in_sizes, int n_in,
                              void* d_out, int out_size)
{
    const float* x      = (const float*)d_in[0];
    const float* w_qkv  = (const float*)d_in[1];
    const float* w_out  = (const float*)d_in[2];
    const float* gamma  = (const float*)d_in[3];
    const float* beta   = (const float*)d_in[4];
    float* out = (float*)d_out;

    dim3 g1(8, NTILES);
    k_qkv_mma<<<g1, 256>>>(x, w_qkv);
    k_scale_fin<<<16, 256>>>();
    k_out<<<1024, 256>>>(w_out, gamma, beta, out);
}

// round 12
// speedup vs baseline: 2.2245x; 2.2245x over previous
#include <cuda_runtime.h>
#include <math.h>
#include <stdint.h>

// ---------------------------------------------------------------------------
// LinearAttention:
//   k_conv_w  : one-time w_qkv -> fragment-ordered tf32 gmem (0.75 MB)
//   k_qkv_mma : TF32 mma.sync GEMM, zero-smem mainloop (A frags from g_wfrag,
//               B frags straight from natural x) + elu + kv reductions
//   k_scale   : deterministic finalize
//   k_out     : measured-good f32x2-FFMA GEMM + fused LayerNorm
// ---------------------------------------------------------------------------

using u64 = unsigned long long;

#define NB   16
#define NC   256
#define NPIX 4096
#define PTILES_PER_B 32
#define NTILES (NB * PTILES_PER_B)

__device__ float    g_qk[(size_t)NB * NC * NPIX];   // elu1(q), [b][c][pix]
__device__ float    g_part_kv[NTILES][NC];
__device__ float    g_part_kk[NTILES][NC];
__device__ float    g_scale[NB * NC];
__device__ uint32_t g_wfrag[8 * 32 * 6 * 128];      // [g][ks32][sec*2+half][128w]

// ------------------------------ helpers ------------------------------------
__device__ __forceinline__ u64 pack2(float x, float y) {
    u64 r; asm("mov.b64 %0, {%1, %2};" : "=l"(r) : "f"(x), "f"(y)); return r;
}
__device__ __forceinline__ void unpack2(u64 v, float &x, float &y) {
    asm("mov.b64 {%0, %1}, %2;" : "=f"(x), "=f"(y) : "l"(v));
}
__device__ __forceinline__ void ffma2(u64 &d, u64 a, u64 b) {
    asm("fma.rn.f32x2 %0, %1, %2, %0;" : "+l"(d) : "l"(a), "l"(b));
}
__device__ __forceinline__ float elu1(float v) { return v > 0.0f ? v + 1.0f : expf(v); }

__device__ __forceinline__ uint32_t f2tf32(float x) {
    uint32_t r; asm("cvt.rna.tf32.f32 %0, %1;" : "=r"(r) : "f"(x)); return r;
}

// m16n8k8 TF32 mma, D += A*B (fp32 accum)
__device__ __forceinline__ void mma_tf32(float* d, const uint32_t* a, const uint32_t* b) {
    asm volatile(
        "mma.sync.aligned.m16n8k8.row.col.f32.tf32.tf32.f32 "
        "{%0,%1,%2,%3}, {%4,%5,%6,%7}, {%8,%9}, {%0,%1,%2,%3};"
        : "+f"(d[0]), "+f"(d[1]), "+f"(d[2]), "+f"(d[3])
        : "r"(a[0]), "r"(a[1]), "r"(a[2]), "r"(a[3]), "r"(b[0]), "r"(b[1]));
}

// ===========================================================================
// Kernel 0: convert w_qkv into fragment-ordered tf32 (inverse of the
// verified-passing Wf store map). Word i:
//   reg=i&3, lane=(i>>2)&31, half=(i>>7)&1, q=i>>8, sec=q%3, r=q/3,
//   ks32=r&31, g=r>>5;  row = sec*256+g*32+half*16+(lane>>2)+8*(reg&1)
//                       col = ks32*8+(lane&3)+4*(reg>>1)
// ===========================================================================
__global__ void k_conv_w(const float* __restrict__ w_qkv)
{
    int i = blockIdx.x * 256 + threadIdx.x;        // 0..196607, grid 768
    int reg  = i & 3;
    int lane = (i >> 2) & 31;
    int half = (i >> 7) & 1;
    int q    = i >> 8;
    int sec  = q % 3;
    int r    = q / 3;
    int ks32 = r & 31;
    int g    = r >> 5;
    int row = sec * 256 + g * 32 + half * 16 + (lane >> 2) + 8 * (reg & 1);
    int col = ks32 * 8 + (lane & 3) + 4 * (reg >> 1);
    g_wfrag[i] = f2tf32(w_qkv[row * 256 + col]);
}

// ===========================================================================
// Kernel 1: TF32 mma QKV GEMM, zero-smem mainloop
//   grid (8, 512); block 256 = 8 warps: (ochalf 2) x (pxq 4)
// ===========================================================================
__global__ __launch_bounds__(256, 2)
void k_qkv_mma(const float* __restrict__ x, const float* __restrict__ w_qkv)
{
    __shared__ float red_kk[32][4], red_kv[32][4];

    const int g    = blockIdx.x;            // 0..7
    const int t    = blockIdx.y;            // 0..511
    const int b    = t >> 5;
    const int p0   = (t & 31) << 7;
    const int tid  = threadIdx.x;
    const int wid  = tid >> 5, lane = tid & 31;
    const int ochalf = wid >> 2;            // 0..1
    const int pxq    = wid & 3;             // 0..3 -> pixels pxq*32..+31
    const int grp = lane >> 2, tig = lane & 3;

    float acc[3][4][4];                     // [section][n-tile][c-reg]
#pragma unroll
    for (int s = 0; s < 3; s++)
#pragma unroll
        for (int n = 0; n < 4; n++)
#pragma unroll
            for (int c = 0; c < 4; c++) acc[s][n][c] = 0.0f;

    // A fragments: fragment-ordered gmem, one uint4 per section per k8-step
    const uint32_t* wslab = g_wfrag + (size_t)g * (32 * 6 * 128)
                          + ochalf * 128 + lane * 4;
    // B fragments: natural x; lane reads x[k0+tig(+4)][p0+pxq*32+n*8+grp]
    const float* xw = x + (size_t)b * NC * NPIX + p0 + pxq * 32 + grp
                    + (size_t)tig * NPIX;

#pragma unroll 4
    for (int ks = 0; ks < 32; ks++) {
        const uint32_t* wp = wslab + ks * 768;     // 6*128 words per k8-step
        uint32_t a[3][4];
        *(uint4*)a[0] = *(const uint4*)(wp);
        *(uint4*)a[1] = *(const uint4*)(wp + 256);
        *(uint4*)a[2] = *(const uint4*)(wp + 512);

        const float* xk  = xw + (size_t)(ks * 8) * NPIX;
        const float* xk4 = xk + (size_t)4 * NPIX;
        uint32_t bf[4][2];
#pragma unroll
        for (int n = 0; n < 4; n++) {
            bf[n][0] = f2tf32(xk [n * 8]);
            bf[n][1] = f2tf32(xk4[n * 8]);
        }
#pragma unroll
        for (int s = 0; s < 3; s++)
#pragma unroll
            for (int n = 0; n < 4; n++)
                mma_tf32(acc[s][n], a[s], bf[n]);
    }

    // ---------------- q epilogue: elu -> g_qk (verified mapping) -----------
    {
        int oc = g * 32 + ochalf * 16 + grp;
        float* dst0 = g_qk + ((size_t)(b * NC + oc)) * NPIX + p0 + pxq * 32;
        float* dst1 = dst0 + (size_t)8 * NPIX;   // row grp+8
#pragma unroll
        for (int n = 0; n < 4; n++) {
            int px = n * 8 + tig * 2;
            float2 lo, hi;
            lo.x = elu1(acc[0][n][0]); lo.y = elu1(acc[0][n][1]);
            hi.x = elu1(acc[0][n][2]); hi.y = elu1(acc[0][n][3]);
            *(float2*)(dst0 + px) = lo;
            *(float2*)(dst1 + px) = hi;
        }
    }

    // ---------------- k/v epilogue: partial sums (verified mapping) --------
    float skk0 = 0.0f, skk1 = 0.0f, skv0 = 0.0f, skv1 = 0.0f;
#pragma unroll
    for (int n = 0; n < 4; n++) {
        float ek;
        ek = elu1(acc[1][n][0]); skk0 += ek; skv0 += ek * acc[2][n][0];
        ek = elu1(acc[1][n][1]); skk0 += ek; skv0 += ek * acc[2][n][1];
        ek = elu1(acc[1][n][2]); skk1 += ek; skv1 += ek * acc[2][n][2];
        ek = elu1(acc[1][n][3]); skk1 += ek; skv1 += ek * acc[2][n][3];
    }
#pragma unroll
    for (int off = 1; off < 4; off <<= 1) {
        skk0 += __shfl_xor_sync(0xFFFFFFFFu, skk0, off);
        skk1 += __shfl_xor_sync(0xFFFFFFFFu, skk1, off);
        skv0 += __shfl_xor_sync(0xFFFFFFFFu, skv0, off);
        skv1 += __shfl_xor_sync(0xFFFFFFFFu, skv1, off);
    }
    if (tig == 0) {
        int r = ochalf * 16 + grp;
        red_kk[r][pxq]     = skk0;  red_kv[r][pxq]     = skv0;
        red_kk[r + 8][pxq] = skk1;  red_kv[r + 8][pxq] = skv1;
    }
    __syncthreads();
    if (tid < 32) {
        float kk = red_kk[tid][0] + red_kk[tid][1] + red_kk[tid][2] + red_kk[tid][3];
        float kv = red_kv[tid][0] + red_kv[tid][1] + red_kv[tid][2] + red_kv[tid][3];
        g_part_kk[t][g * 32 + tid] = kk;
        g_part_kv[t][g * 32 + tid] = kv;
    }
}

// ===========================================================================
// Kernel 2: finalize scale[b][c]  (deterministic serial sum)
// ===========================================================================
__global__ void k_scale_fin()
{
    int idx = blockIdx.x * 256 + threadIdx.x;
    int b = idx >> 8, c = idx & 255;
    float skv = 0.0f, skk = 0.0f;
#pragma unroll
    for (int i = 0; i < PTILES_PER_B; i++) {
        skv += g_part_kv[b * PTILES_PER_B + i][c];
        skk += g_part_kk[b * PTILES_PER_B + i][c];
    }
    g_scale[idx] = skv / fmaxf(skk, 1e-6f);
}

// ===========================================================================
// Kernel 3: out GEMM + fused LayerNorm (round-3 measured version)
// ===========================================================================
__global__ __launch_bounds__(256, 2)
void k_out(const float* __restrict__ w_out, const float* __restrict__ gamma,
           const float* __restrict__ beta, float* __restrict__ out)
{
    __shared__ alignas(16) float As[32][64];
    __shared__ alignas(16) float Bs[32][257];
    __shared__ float sscale[256], sgamma[256], sbeta[256];
    __shared__ float smu[64], srstd[64];

    const int blk  = blockIdx.x;
    const int b    = blk >> 6;
    const int p0   = (blk & 63) << 6;
    const int tid  = threadIdx.x;
    const int pixT = tid & 7;
    const int ocT  = tid >> 3;
    const int lane = tid & 31;
    const int warp = tid >> 5;

    sscale[tid] = g_scale[b * NC + tid];
    sgamma[tid] = gamma[tid];
    sbeta[tid]  = beta[tid];
    __syncthreads();

    u64 acc[8][4];
#pragma unroll
    for (int j = 0; j < 8; j++)
#pragma unroll
        for (int i = 0; i < 4; i++) acc[j][i] = 0ull;

    const float* qb = g_qk + (size_t)b * NC * NPIX + p0;

    for (int kc = 0; kc < 256; kc += 32) {
#pragma unroll
        for (int r = 0; r < 2; r++) {
            int f = tid + 256 * r;
            int k = f >> 4, q = f & 15;
            float4 v = *(const float4*)(qb + (size_t)(kc + k) * NPIX + q * 4);
            float s = sscale[kc + k];
            v.x *= s; v.y *= s; v.z *= s; v.w *= s;
            *(float4*)&As[k][q * 4] = v;
        }
#pragma unroll
        for (int r = 0; r < 8; r++) {
            int f = tid + 256 * r;
            int o = f >> 3, q = f & 7;
            float4 v = *(const float4*)(w_out + (size_t)o * 256 + kc + q * 4);
            Bs[q * 4 + 0][o] = v.x;
            Bs[q * 4 + 1][o] = v.y;
            Bs[q * 4 + 2][o] = v.z;
            Bs[q * 4 + 3][o] = v.w;
        }
        __syncthreads();

#pragma unroll 8
        for (int kk = 0; kk < 32; kk++) {
            u64 av[4];
#pragma unroll
            for (int i = 0; i < 4; i++)
                av[i] = *(const u64*)&As[kk][16 * i + 2 * pixT];
#pragma unroll
            for (int j = 0; j < 8; j++) {
                float bs = Bs[kk][ocT * 8 + j];
                u64 bv = pack2(bs, bs);
#pragma unroll
                for (int i = 0; i < 4; i++) ffma2(acc[j][i], av[i], bv);
            }
        }
        __syncthreads();
    }

    float ps[4][2], pss[4][2];
#pragma unroll
    for (int i = 0; i < 4; i++) { ps[i][0] = ps[i][1] = 0.0f; pss[i][0] = pss[i][1] = 0.0f; }
#pragma unroll
    for (int j = 0; j < 8; j++)
#pragma unroll
        for (int i = 0; i < 4; i++) {
            float v0, v1; unpack2(acc[j][i], v0, v1);
            ps[i][0] += v0;  pss[i][0] += v0 * v0;
            ps[i][1] += v1;  pss[i][1] += v1 * v1;
        }
#pragma unroll
    for (int off = 8; off < 32; off <<= 1)
#pragma unroll
        for (int i = 0; i < 4; i++) {
            ps[i][0]  += __shfl_xor_sync(0xFFFFFFFFu, ps[i][0],  off);
            ps[i][1]  += __shfl_xor_sync(0xFFFFFFFFu, ps[i][1],  off);
            pss[i][0] += __shfl_xor_sync(0xFFFFFFFFu, pss[i][0], off);
            pss[i][1] += __shfl_xor_sync(0xFFFFFFFFu, pss[i][1], off);
        }
    float (*redA)[64] = (float(*)[64])&As[0][0];
    float (*redB)[64] = (float(*)[64])&As[16][0];
    __syncthreads();
    if (lane < 8) {
#pragma unroll
        for (int i = 0; i < 4; i++) {
            int p = 16 * i + 2 * lane;
            redA[warp][p]     = ps[i][0];
            redA[warp][p + 1] = ps[i][1];
            redB[warp][p]     = pss[i][0];
            redB[warp][p + 1] = pss[i][1];
        }
    }
    __syncthreads();
    if (tid < 64) {
        float s = 0.0f, ss = 0.0f;
#pragma unroll
        for (int w = 0; w < 8; w++) { s += redA[w][tid]; ss += redB[w][tid]; }
        float mu  = s * (1.0f / 256.0f);
        float var = ss * (1.0f / 256.0f) - mu * mu;
        smu[tid]   = mu;
        srstd[tid] = rsqrtf(var + 1e-5f);
    }
    __syncthreads();

    float* ob = out + (size_t)b * NC * NPIX + p0;
#pragma unroll
    for (int j = 0; j < 8; j++) {
        int oc = ocT * 8 + j;
        float gm = sgamma[oc], bt = sbeta[oc];
        float* dst = ob + (size_t)oc * NPIX;
#pragma unroll
        for (int i = 0; i < 4; i++) {
            int p = 16 * i + 2 * pixT;
            float v0, v1; unpack2(acc[j][i], v0, v1);
            float2 o2;
            o2.x = (v0 - smu[p])     * srstd[p]     * gm + bt;
            o2.y = (v1 - smu[p + 1]) * srstd[p + 1] * gm + bt;
            *(float2*)(dst + p) = o2;
        }
    }
}

// ===========================================================================
extern "C" void kernel_launch(void* const* d_in, const int* in_sizes, int n_in,
                              void* d_out, int out_size)
{
    const float* x      = (const float*)d_in[0];
    const float* w_qkv  = (const float*)d_in[1];
    const float* w_out  = (const float*)d_in[2];
    const float* gamma  = (const float*)d_in[3];
    const float* beta   = (const float*)d_in[4];
    float* out = (float*)d_out;

    k_conv_w<<<768, 256>>>(w_qkv);
    dim3 g1(8, NTILES);
    k_qkv_mma<<<g1, 256>>>(x, w_qkv);
    k_scale_fin<<<16, 256>>>();
    k_out<<<1024, 256>>>(w_out, gamma, beta, out);
}

// round 14
// speedup vs baseline: 2.7847x; 1.2518x over previous
#include <cuda_runtime.h>
#include <math.h>
#include <stdint.h>

// ---------------------------------------------------------------------------
// LinearAttention — full TF32 mma.sync pipeline (zero-smem mainloops):
//   k_conv_w  : w_qkv  -> fragment-ordered tf32 gmem (verified map)
//   k_conv_w2 : w_out  -> fragment-ordered tf32 gmem (same algebra)
//   k_qkv_mma : qkv GEMM + elu + kv reductions   (verified, ~240us)
//   k_scale   : deterministic finalize
//   k_out_mma : out GEMM (scale folded into B) + fused LayerNorm
// ---------------------------------------------------------------------------

using u64 = unsigned long long;

#define NB   16
#define NC   256
#define NPIX 4096
#define PTILES_PER_B 32
#define NTILES (NB * PTILES_PER_B)

__device__ float    g_qk[(size_t)NB * NC * NPIX];   // elu1(q), [b][c][pix]
__device__ float    g_part_kv[NTILES][NC];
__device__ float    g_part_kk[NTILES][NC];
__device__ float    g_scale[NB * NC];
__device__ uint32_t g_wfrag[8 * 32 * 6 * 128];      // qkv W frags
__device__ uint32_t g_w2frag[32 * 16 * 128];        // out  W frags [ks][mtile][128]

// ------------------------------ helpers ------------------------------------
__device__ __forceinline__ float elu1(float v) { return v > 0.0f ? v + 1.0f : expf(v); }

__device__ __forceinline__ uint32_t f2tf32(float x) {
    uint32_t r; asm("cvt.rna.tf32.f32 %0, %1;" : "=r"(r) : "f"(x)); return r;
}

// m16n8k8 TF32 mma, D += A*B (fp32 accum)
__device__ __forceinline__ void mma_tf32(float* d, const uint32_t* a, const uint32_t* b) {
    asm volatile(
        "mma.sync.aligned.m16n8k8.row.col.f32.tf32.tf32.f32 "
        "{%0,%1,%2,%3}, {%4,%5,%6,%7}, {%8,%9}, {%0,%1,%2,%3};"
        : "+f"(d[0]), "+f"(d[1]), "+f"(d[2]), "+f"(d[3])
        : "r"(a[0]), "r"(a[1]), "r"(a[2]), "r"(a[3]), "r"(b[0]), "r"(b[1]));
}

// ===========================================================================
// Kernel 0a: w_qkv -> fragment order (verified in hardware, round 12)
// ===========================================================================
__global__ void k_conv_w(const float* __restrict__ w_qkv)
{
    int i = blockIdx.x * 256 + threadIdx.x;        // grid 768
    int reg  = i & 3;
    int lane = (i >> 2) & 31;
    int half = (i >> 7) & 1;
    int q    = i >> 8;
    int sec  = q % 3;
    int r    = q / 3;
    int ks32 = r & 31;
    int g    = r >> 5;
    int row = sec * 256 + g * 32 + half * 16 + (lane >> 2) + 8 * (reg & 1);
    int col = ks32 * 8 + (lane & 3) + 4 * (reg >> 1);
    g_wfrag[i] = f2tf32(w_qkv[row * 256 + col]);
}

// ===========================================================================
// Kernel 0b: w_out -> fragment order [ks32][mtile16][128 words]
//   word i: reg=i&3, lane=(i>>2)&31, mt=(i>>7)&15, ks=i>>11
//   row = mt*16 + (lane>>2) + 8*(reg&1);  col = ks*8 + (lane&3) + 4*(reg>>1)
// ===========================================================================
__global__ void k_conv_w2(const float* __restrict__ w_out)
{
    int i = blockIdx.x * 256 + threadIdx.x;        // grid 256 -> 65536
    int reg  = i & 3;
    int lane = (i >> 2) & 31;
    int mt   = (i >> 7) & 15;
    int ks   = i >> 11;
    int row = mt * 16 + (lane >> 2) + 8 * (reg & 1);
    int col = ks * 8 + (lane & 3) + 4 * (reg >> 1);
    g_w2frag[i] = f2tf32(w_out[row * 256 + col]);
}

// ===========================================================================
// Kernel 1: TF32 mma QKV GEMM, zero-smem mainloop (verified, unchanged)
// ===========================================================================
__global__ __launch_bounds__(256, 2)
void k_qkv_mma(const float* __restrict__ x)
{
    __shared__ float red_kk[32][4], red_kv[32][4];

    const int g    = blockIdx.x;
    const int t    = blockIdx.y;
    const int b    = t >> 5;
    const int p0   = (t & 31) << 7;
    const int tid  = threadIdx.x;
    const int wid  = tid >> 5, lane = tid & 31;
    const int ochalf = wid >> 2;
    const int pxq    = wid & 3;
    const int grp = lane >> 2, tig = lane & 3;

    float acc[3][4][4];
#pragma unroll
    for (int s = 0; s < 3; s++)
#pragma unroll
        for (int n = 0; n < 4; n++)
#pragma unroll
            for (int c = 0; c < 4; c++) acc[s][n][c] = 0.0f;

    const uint32_t* wslab = g_wfrag + (size_t)g * (32 * 6 * 128)
                          + ochalf * 128 + lane * 4;
    const float* xw = x + (size_t)b * NC * NPIX + p0 + pxq * 32 + grp
                    + (size_t)tig * NPIX;

#pragma unroll 4
    for (int ks = 0; ks < 32; ks++) {
        const uint32_t* wp = wslab + ks * 768;
        uint32_t a[3][4];
        *(uint4*)a[0] = *(const uint4*)(wp);
        *(uint4*)a[1] = *(const uint4*)(wp + 256);
        *(uint4*)a[2] = *(const uint4*)(wp + 512);

        const float* xk  = xw + (size_t)(ks * 8) * NPIX;
        const float* xk4 = xk + (size_t)4 * NPIX;
        uint32_t bf[4][2];
#pragma unroll
        for (int n = 0; n < 4; n++) {
            bf[n][0] = f2tf32(xk [n * 8]);
            bf[n][1] = f2tf32(xk4[n * 8]);
        }
#pragma unroll
        for (int s = 0; s < 3; s++)
#pragma unroll
            for (int n = 0; n < 4; n++)
                mma_tf32(acc[s][n], a[s], bf[n]);
    }

    // q epilogue
    {
        int oc = g * 32 + ochalf * 16 + grp;
        float* dst0 = g_qk + ((size_t)(b * NC + oc)) * NPIX + p0 + pxq * 32;
        float* dst1 = dst0 + (size_t)8 * NPIX;
#pragma unroll
        for (int n = 0; n < 4; n++) {
            int px = n * 8 + tig * 2;
            float2 lo, hi;
            lo.x = elu1(acc[0][n][0]); lo.y = elu1(acc[0][n][1]);
            hi.x = elu1(acc[0][n][2]); hi.y = elu1(acc[0][n][3]);
            *(float2*)(dst0 + px) = lo;
            *(float2*)(dst1 + px) = hi;
        }
    }

    // k/v epilogue
    float skk0 = 0.0f, skk1 = 0.0f, skv0 = 0.0f, skv1 = 0.0f;
#pragma unroll
    for (int n = 0; n < 4; n++) {
        float ek;
        ek = elu1(acc[1][n][0]); skk0 += ek; skv0 += ek * acc[2][n][0];
        ek = elu1(acc[1][n][1]); skk0 += ek; skv0 += ek * acc[2][n][1];
        ek = elu1(acc[1][n][2]); skk1 += ek; skv1 += ek * acc[2][n][2];
        ek = elu1(acc[1][n][3]); skk1 += ek; skv1 += ek * acc[2][n][3];
    }
#pragma unroll
    for (int off = 1; off < 4; off <<= 1) {
        skk0 += __shfl_xor_sync(0xFFFFFFFFu, skk0, off);
        skk1 += __shfl_xor_sync(0xFFFFFFFFu, skk1, off);
        skv0 += __shfl_xor_sync(0xFFFFFFFFu, skv0, off);
        skv1 += __shfl_xor_sync(0xFFFFFFFFu, skv1, off);
    }
    if (tig == 0) {
        int r = ochalf * 16 + grp;
        red_kk[r][pxq]     = skk0;  red_kv[r][pxq]     = skv0;
        red_kk[r + 8][pxq] = skk1;  red_kv[r + 8][pxq] = skv1;
    }
    __syncthreads();
    if (tid < 32) {
        float kk = red_kk[tid][0] + red_kk[tid][1] + red_kk[tid][2] + red_kk[tid][3];
        float kv = red_kv[tid][0] + red_kv[tid][1] + red_kv[tid][2] + red_kv[tid][3];
        g_part_kk[t][g * 32 + tid] = kk;
        g_part_kv[t][g * 32 + tid] = kv;
    }
}

// ===========================================================================
// Kernel 2: finalize scale[b][c]
// ===========================================================================
__global__ void k_scale_fin()
{
    int idx = blockIdx.x * 256 + threadIdx.x;
    int b = idx >> 8, c = idx & 255;
    float skv = 0.0f, skk = 0.0f;
#pragma unroll
    for (int i = 0; i < PTILES_PER_B; i++) {
        skv += g_part_kv[b * PTILES_PER_B + i][c];
        skk += g_part_kk[b * PTILES_PER_B + i][c];
    }
    g_scale[idx] = skv / fmaxf(skk, 1e-6f);
}

// ===========================================================================
// Kernel 3: TF32 mma out GEMM + fused LayerNorm, zero-smem mainloop
//   grid 1024 = (b, 64-px tile); block 256 = 8 warps = 4 ocquad x 2 pxhalf
//   Per warp: 4 m16-tiles (64 oc) x 4 n8-tiles (32 px), K=256.
// ===========================================================================
__global__ __launch_bounds__(256, 2)
void k_out_mma(const float* __restrict__ gamma, const float* __restrict__ beta,
               float* __restrict__ out)
{
    __shared__ float sscale[256], sgamma[256], sbeta[256];
    __shared__ float red_s[64][4], red_ss[64][4];
    __shared__ float smu[64], srstd[64];

    const int blk  = blockIdx.x;
    const int b    = blk >> 6;
    const int p0   = (blk & 63) << 6;
    const int tid  = threadIdx.x;
    const int wid  = tid >> 5, lane = tid & 31;
    const int ocquad = wid >> 1;            // 0..3 -> oc 64*ocquad..
    const int pxhalf = wid & 1;             // 0..1 -> px 32*pxhalf..
    const int grp = lane >> 2, tig = lane & 3;

    sscale[tid] = g_scale[b * NC + tid];
    sgamma[tid] = gamma[tid];
    sbeta[tid]  = beta[tid];
    __syncthreads();

    float acc[4][4][4];                     // [m-tile][n-tile][c-reg]
#pragma unroll
    for (int m = 0; m < 4; m++)
#pragma unroll
        for (int n = 0; n < 4; n++)
#pragma unroll
            for (int c = 0; c < 4; c++) acc[m][n][c] = 0.0f;

    const uint32_t* wslab = g_w2frag + ocquad * 512 + lane * 4;
    // B: qk[k][px]*scale[k]; lane reads row k0+tig(+4), col p0+pxhalf*32+8n+grp
    const float* qw = g_qk + (size_t)b * NC * NPIX + p0 + pxhalf * 32 + grp
                    + (size_t)tig * NPIX;

#pragma unroll 4
    for (int ks = 0; ks < 32; ks++) {
        const uint32_t* wp = wslab + ks * 2048;
        uint32_t a[4][4];
#pragma unroll
        for (int m = 0; m < 4; m++)
            *(uint4*)a[m] = *(const uint4*)(wp + m * 128);

        float s0 = sscale[ks * 8 + tig];
        float s1 = sscale[ks * 8 + tig + 4];
        const float* qk  = qw + (size_t)(ks * 8) * NPIX;
        const float* qk4 = qk + (size_t)4 * NPIX;
        uint32_t bf[4][2];
#pragma unroll
        for (int n = 0; n < 4; n++) {
            bf[n][0] = f2tf32(qk [n * 8] * s0);
            bf[n][1] = f2tf32(qk4[n * 8] * s1);
        }
#pragma unroll
        for (int m = 0; m < 4; m++)
#pragma unroll
            for (int n = 0; n < 4; n++)
                mma_tf32(acc[m][n], a[m], bf[n]);
    }

    // ---------------- fused LayerNorm over 256 channels --------------------
    float ps[4][2], pss[4][2];
#pragma unroll
    for (int n = 0; n < 4; n++) { ps[n][0] = ps[n][1] = 0.0f; pss[n][0] = pss[n][1] = 0.0f; }
#pragma unroll
    for (int m = 0; m < 4; m++)
#pragma unroll
        for (int n = 0; n < 4; n++) {
            float v0 = acc[m][n][0], v1 = acc[m][n][1];
            float v2 = acc[m][n][2], v3 = acc[m][n][3];
            ps[n][0] += v0 + v2;  pss[n][0] += v0 * v0 + v2 * v2;
            ps[n][1] += v1 + v3;  pss[n][1] += v1 * v1 + v3 * v3;
        }
    // reduce over grp (lanes sharing tig): xor offsets 4, 8, 16
#pragma unroll
    for (int off = 4; off < 32; off <<= 1)
#pragma unroll
        for (int n = 0; n < 4; n++) {
            ps[n][0]  += __shfl_xor_sync(0xFFFFFFFFu, ps[n][0],  off);
            ps[n][1]  += __shfl_xor_sync(0xFFFFFFFFu, ps[n][1],  off);
            pss[n][0] += __shfl_xor_sync(0xFFFFFFFFu, pss[n][0], off);
            pss[n][1] += __shfl_xor_sync(0xFFFFFFFFu, pss[n][1], off);
        }
    if (lane < 4) {                         // lane == tig, grp-group 0
#pragma unroll
        for (int n = 0; n < 4; n++) {
            int px = pxhalf * 32 + n * 8 + lane * 2;
            red_s [px][ocquad]     = ps[n][0];
            red_s [px + 1][ocquad] = ps[n][1];
            red_ss[px][ocquad]     = pss[n][0];
            red_ss[px + 1][ocquad] = pss[n][1];
        }
    }
    __syncthreads();
    if (tid < 64) {
        float s  = red_s [tid][0] + red_s [tid][1] + red_s [tid][2] + red_s [tid][3];
        float ss = red_ss[tid][0] + red_ss[tid][1] + red_ss[tid][2] + red_ss[tid][3];
        float mu  = s * (1.0f / 256.0f);
        float var = ss * (1.0f / 256.0f) - mu * mu;
        smu[tid]   = mu;
        srstd[tid] = rsqrtf(var + 1e-5f);
    }
    __syncthreads();

    // normalized writes (hardware-verified C-map pattern)
    float* ob = out + (size_t)b * NC * NPIX + p0 + pxhalf * 32;
#pragma unroll
    for (int m = 0; m < 4; m++) {
        int oc0 = ocquad * 64 + m * 16 + grp;
        float gm0 = sgamma[oc0],     bt0 = sbeta[oc0];
        float gm1 = sgamma[oc0 + 8], bt1 = sbeta[oc0 + 8];
        float* dst0 = ob + (size_t)oc0 * NPIX;
        float* dst1 = dst0 + (size_t)8 * NPIX;
#pragma unroll
        for (int n = 0; n < 4; n++) {
            int px  = n * 8 + tig * 2;                 // within 32-px half
            int pl  = pxhalf * 32 + px;                // LN index
            float m0 = smu[pl], m1 = smu[pl + 1];
            float r0 = srstd[pl], r1 = srstd[pl + 1];
            float2 lo, hi;
            lo.x = (acc[m][n][0] - m0) * r0 * gm0 + bt0;
            lo.y = (acc[m][n][1] - m1) * r1 * gm0 + bt0;
            hi.x = (acc[m][n][2] - m0) * r0 * gm1 + bt1;
            hi.y = (acc[m][n][3] - m1) * r1 * gm1 + bt1;
            *(float2*)(dst0 + px) = lo;
            *(float2*)(dst1 + px) = hi;
        }
    }
}

// ===========================================================================
extern "C" void kernel_launch(void* const* d_in, const int* in_sizes, int n_in,
                              void* d_out, int out_size)
{
    const float* x      = (const float*)d_in[0];
    const float* w_qkv  = (const float*)d_in[1];
    const float* w_out  = (const float*)d_in[2];
    const float* gamma  = (const float*)d_in[3];
    const float* beta   = (const float*)d_in[4];
    float* out = (float*)d_out;

    k_conv_w<<<768, 256>>>(w_qkv);
    k_conv_w2<<<256, 256>>>(w_out);
    dim3 g1(8, NTILES);
    k_qkv_mma<<<g1, 256>>>(x);
    k_scale_fin<<<16, 256>>>();
    k_out_mma<<<1024, 256>>>(gamma, beta, out);
}